// round 15
// baseline (speedup 1.0000x reference)
#include <cuda_runtime.h>
#include <cstdint>

#define B 8
#define N 100000
#define V 40
#define NBINS 64000
#define NTILES 63
#define TILE 1024
#define PB_F4 1296000                // float4s per batch in nbr table

// Output layout (float32 elements)
#define O_IDX  0
#define O_HASH 800000
#define O_NBR  1600000
#define O_MASK 43072000

#define NBR_BLOCKS 444               // 3 per SM — more store MLP, still headroom
#define NBR_THREADS 256

// ---- scratch ----
__device__ int g_pack[B * N];        // bin | (rank << 16) per point
__device__ int g_hist[B * NBINS];    // counts -> offsets; re-zeroed in finalize
__device__ int g_cursor[B * NBINS];  // offsets copy (finalize segment bounds)
__device__ int g_sorted[B * N];
__device__ int g_tsum[B * NTILES];

// ---------------------------------------------------------------------------
// bin: 4 points/thread via float4 loads; atomicAdd returns rank-in-bin.
// bin (<64000) and rank (<~30) packed into one int.
__global__ void bin_kernel(const float* __restrict__ pts) {
    int gi = blockIdx.x * blockDim.x + threadIdx.x;
    if (gi >= (B * N) / 4) return;
    const float4* p4 = (const float4*)pts;
    float4 f0 = __ldg(&p4[3 * gi]);
    float4 f1 = __ldg(&p4[3 * gi + 1]);
    float4 f2 = __ldg(&p4[3 * gi + 2]);
    int b = gi / (N / 4);
    float px[4] = { f0.x, f0.w, f1.z, f2.y };
    float py[4] = { f0.y, f1.x, f1.w, f2.z };
    float pz[4] = { f0.z, f1.y, f2.x, f2.w };
    int bins[4], pk[4];
    #pragma unroll
    for (int k = 0; k < 4; k++) {
        int cx = (int)(px[k] * (float)(V - 1));
        int cy = (int)(py[k] * (float)(V - 1));
        int cz = (int)(pz[k] * (float)(V - 1));
        bins[k] = cx * (V * V) + cy * V + cz;
    }
    #pragma unroll
    for (int k = 0; k < 4; k++) {
        int r = atomicAdd(&g_hist[b * NBINS + bins[k]], 1);
        pk[k] = bins[k] | (r << 16);
    }
    *(int4*)(g_pack + 4 * gi) = make_int4(pk[0], pk[1], pk[2], pk[3]);
}

// ---- 2-phase scan: scanA tile sums; scanC computes its own base ------------
__global__ void scanA_kernel() {
    int b = blockIdx.x / NTILES;
    int t = blockIdx.x % NTILES;
    int tb = t * TILE + threadIdx.x * 4;
    int s = 0;
    if (tb < NBINS) {
        int4 v = *(const int4*)(g_hist + b * NBINS + tb);
        s = v.x + v.y + v.z + v.w;
    }
    #pragma unroll
    for (int o = 16; o > 0; o >>= 1) s += __shfl_down_sync(0xFFFFFFFFu, s, o);
    __shared__ int ws[8];
    int lane = threadIdx.x & 31, warp = threadIdx.x >> 5;
    if (lane == 0) ws[warp] = s;
    __syncthreads();
    if (threadIdx.x == 0) {
        int tot = 0;
        #pragma unroll
        for (int w = 0; w < 8; w++) tot += ws[w];
        g_tsum[blockIdx.x] = tot;
    }
}

// scanC: warp 0 sums preceding tile sums for the base; block scans its tile;
// writes offsets + cursors + mask.
__global__ void scanC_kernel(float* __restrict__ out) {
    int b = blockIdx.x / NTILES;
    int t = blockIdx.x % NTILES;
    int tid = threadIdx.x;
    __shared__ int ws[8];
    __shared__ int s_base;

    if (tid < 32) {
        int v = 0;
        if (tid < t)      v += g_tsum[b * NTILES + tid];
        if (tid + 32 < t) v += g_tsum[b * NTILES + tid + 32];
        #pragma unroll
        for (int o = 16; o > 0; o >>= 1) v += __shfl_down_sync(0xFFFFFFFFu, v, o);
        if (tid == 0) s_base = v;
    }

    int tb = t * TILE + tid * 4;
    int4 v = make_int4(0, 0, 0, 0);
    if (tb < NBINS) v = *(const int4*)(g_hist + b * NBINS + tb);
    int tsum = v.x + v.y + v.z + v.w;
    int lane = tid & 31, warp = tid >> 5;
    int x = tsum;
    #pragma unroll
    for (int o = 1; o < 32; o <<= 1) {
        int tt = __shfl_up_sync(0xFFFFFFFFu, x, o);
        if (lane >= o) x += tt;
    }
    if (lane == 31) ws[warp] = x;
    __syncthreads();
    int woff = 0;
    #pragma unroll
    for (int w = 0; w < 8; w++) woff += (w < warp) ? ws[w] : 0;
    int base = s_base + woff + x - tsum;
    if (tb < NBINS) {
        int4 o4;
        o4.x = base;
        o4.y = base + v.x;
        o4.z = base + v.x + v.y;
        o4.w = base + v.x + v.y + v.z;
        *(int4*)(g_hist   + b * NBINS + tb) = o4;
        *(int4*)(g_cursor + b * NBINS + tb) = o4;
        float4 m4;
        m4.x = (v.x > 0 && o4.x + v.x < N) ? 1.0f : 0.0f;
        m4.y = (v.y > 0 && o4.y + v.y < N) ? 1.0f : 0.0f;
        m4.z = (v.z > 0 && o4.z + v.z < N) ? 1.0f : 0.0f;
        m4.w = (v.w > 0 && o4.w + v.w < N) ? 1.0f : 0.0f;
        *(float4*)(out + O_MASK + b * NBINS + tb) = m4;
    }
}

// ---------------------------------------------------------------------------
// scatter: NO atomics. pos = offset[bin] + rank (unpacked from g_pack).
__global__ void scatter_kernel() {
    int gi = blockIdx.x * blockDim.x + threadIdx.x;
    if (gi >= (B * N) / 4) return;
    int i0 = gi * 4;
    int b = gi / (N / 4);
    int4 pb = *(const int4*)(g_pack + i0);
    int pk[4] = { pb.x, pb.y, pb.z, pb.w };
    int pos[4];
    #pragma unroll
    for (int k = 0; k < 4; k++) {
        int bin = pk[k] & 0xFFFF;
        int rnk = pk[k] >> 16;
        pos[k] = g_hist[b * NBINS + bin] + rnk;
    }
    int nbase = i0 - b * N;
    #pragma unroll
    for (int k = 0; k < 4; k++)
        g_sorted[b * N + pos[k]] = nbase + k;
}

// ---------------------------------------------------------------------------
// finalize: stable fixup (count>=2 only) + idx/hash writes; re-zeroes g_hist.
__global__ void finalize_kernel(float* __restrict__ out) {
    int t = blockIdx.x * blockDim.x + threadIdx.x;
    if (t >= B * NBINS) return;
    int b = t / NBINS;
    int bin = t - b * NBINS;
    int s = g_cursor[t];
    int e = (bin == NBINS - 1) ? N : g_cursor[t + 1];
    g_hist[t] = 0;                        // restore count invariant for replay
    if (e == s) return;
    int* seg = g_sorted + b * N;

    if (e - s >= 2) {
        for (int a = s + 1; a < e; a++) {
            int key = seg[a];
            int j = a - 1;
            while (j >= s && seg[j] > key) { seg[j + 1] = seg[j]; j--; }
            seg[j + 1] = key;
        }
    }

    int cx = bin / (V * V);
    int cy = (bin / V) % V;
    int cz = bin % V;
    float h = (float)(cx * 10000 + cy * 100 + cz);
    for (int j = s; j < e; j++) {
        out[O_IDX  + b * N + j] = (float)seg[j];
        out[O_HASH + b * N + j] = h;
    }
}

// ---------------------------------------------------------------------------
// neighbour table: PERSISTENT grid-stride kernel, 3 blocks/SM so chain
// kernels co-reside and overlap. One q = one float4 -> 8 batch copies.
__global__ void __launch_bounds__(NBR_THREADS, 3) neighbour_kernel(
    float* __restrict__ out) {
    __shared__ int   s_sel[81];
    __shared__ float s_add[81];
    if (threadIdx.x < 81) {
        int j = threadIdx.x;
        int c = j % 3, m = j / 3;
        int d = (c == 0) ? (m / 9 - 1) : (c == 1) ? ((m / 3) % 3 - 1) : (m % 3 - 1);
        s_sel[j] = c;
        s_add[j] = (float)d;
    }
    __syncthreads();

    const int stride = NBR_BLOCKS * NBR_THREADS;
    float4* pout = (float4*)(out + O_NBR);

    for (int q = blockIdx.x * NBR_THREADS + threadIdx.x; q < PB_F4; q += stride) {
        int e0  = q * 4;
        int vox = e0 / 81;
        int j0  = e0 - vox * 81;
        int x = vox / (V * V);
        int r = vox - x * (V * V);
        int y = r / V;
        int z = r - y * V;
        int zn = z + 1, yn = y, xn = x;
        if (zn == V) { zn = 0; yn = y + 1; if (yn == V) { yn = 0; xn = x + 1; } }
        float xf = (float)x, yf = (float)y, zf = (float)z;
        float xf1 = (float)xn, yf1 = (float)yn, zf1 = (float)zn;

        float4 v;
        float* vp = &v.x;
        #pragma unroll
        for (int k = 0; k < 4; k++) {
            int jk = j0 + k;
            bool w = jk >= 81;
            int jj = w ? jk - 81 : jk;
            int sel = s_sel[jj];
            float cx = (sel == 0) ? (w ? xf1 : xf)
                     : (sel == 1) ? (w ? yf1 : yf)
                                  : (w ? zf1 : zf);
            vp[k] = cx + s_add[jj];
        }

        #pragma unroll
        for (int b = 0; b < B; b++) __stcs(&pout[q + (size_t)b * PB_F4], v);
    }
}

// ---------------------------------------------------------------------------
extern "C" void kernel_launch(void* const* d_in, const int* in_sizes, int n_in,
                              void* d_out, int out_size) {
    const float* pts = (const float*)d_in[0];
    float* out = (float*)d_out;

    static cudaStream_t s_chain = nullptr, s_nbr = nullptr;
    static cudaEvent_t ev_fork = nullptr, ev_a = nullptr, ev_b = nullptr;
    if (s_chain == nullptr) {
        int lo = 0, hi = 0;
        cudaDeviceGetStreamPriorityRange(&lo, &hi);   // hi = greatest priority
        cudaStreamCreateWithPriority(&s_chain, cudaStreamNonBlocking, hi);
        cudaStreamCreateWithPriority(&s_nbr,   cudaStreamNonBlocking, lo);
        cudaEventCreateWithFlags(&ev_fork, cudaEventDisableTiming);
        cudaEventCreateWithFlags(&ev_a,    cudaEventDisableTiming);
        cudaEventCreateWithFlags(&ev_b,    cudaEventDisableTiming);
    }

    // fork from legacy stream
    cudaEventRecord(ev_fork, 0);
    cudaStreamWaitEvent(s_nbr,   ev_fork, 0);
    cudaStreamWaitEvent(s_chain, ev_fork, 0);

    // LOW priority: persistent nbr writer — 3 blocks/SM
    neighbour_kernel<<<NBR_BLOCKS, NBR_THREADS, 0, s_nbr>>>(out);
    cudaEventRecord(ev_b, s_nbr);

    // HIGH priority: sort chain — co-resident with nbr
    bin_kernel     <<<(B * N / 4 + 255) / 256, 256, 0, s_chain>>>(pts);
    scanA_kernel   <<<B * NTILES, 256, 0, s_chain>>>();
    scanC_kernel   <<<B * NTILES, 256, 0, s_chain>>>(out);
    scatter_kernel <<<(B * N / 4 + 255) / 256, 256, 0, s_chain>>>();
    finalize_kernel<<<(B * NBINS + 255) / 256, 256, 0, s_chain>>>(out);
    cudaEventRecord(ev_a, s_chain);

    // join to legacy stream
    cudaStreamWaitEvent(0, ev_a, 0);
    cudaStreamWaitEvent(0, ev_b, 0);
}